// round 8
// baseline (speedup 1.0000x reference)
#include <cuda_runtime.h>
#include <cstdint>

#define NNODES    50000
#define NROWS_PAD 50048
#define NEDGES    100000
#define DIM       768
#define NOUT      1536       // T cols: [x@Wl^T (768) | x@Wr^T (768)]

// ---- scratch (allocation-free rule: __device__ globals) -------------------
__device__ float g_T[(size_t)NROWS_PAD * NOUT];             // 307 MB
__device__ float g_A[(size_t)NROWS_PAD * DIM];              // 154 MB (tf32-rounded)
__device__ float g_W1[(size_t)NOUT * DIM];                  // 4.7 MB
__device__ float g_W2[(size_t)NOUT * DIM];                  // 4.7 MB
__device__ int   g_cnt[NNODES];
__device__ int   g_off[NNODES + 1];
__device__ int   g_cur[NNODES];
__device__ int   g_csr_src[NEDGES];

// ---------------------------------------------------------------------------
__device__ __forceinline__ uint32_t smem_u32(const void* p) {
    uint32_t a;
    asm("{ .reg .u64 t; cvta.to.shared.u64 t, %1; cvt.u32.u64 %0, t; }"
        : "=r"(a) : "l"(p));
    return a;
}
__device__ __forceinline__ float to_tf32(float f) {
    uint32_t u;
    asm("cvt.rna.tf32.f32 %0, %1;" : "=r"(u) : "f"(f));
    return __uint_as_float(u);
}

// ---------------------------------------------------------------------------
// CSR build
// ---------------------------------------------------------------------------
__global__ void zero_int(int* __restrict__ p, int n) {
    int i = blockIdx.x * blockDim.x + threadIdx.x;
    if (i < n) p[i] = 0;
}
__global__ void count_deg(const int* __restrict__ ei, int* __restrict__ cnt) {
    int e = blockIdx.x * blockDim.x + threadIdx.x;
    if (e < NEDGES) atomicAdd(&cnt[ei[NEDGES + e]], 1);
}
__global__ void __launch_bounds__(1024) exscan(
    const int* __restrict__ cnt, int* __restrict__ off, int* __restrict__ cur)
{
    __shared__ int s[1024];
    __shared__ int carry;
    if (threadIdx.x == 0) carry = 0;
    __syncthreads();
    for (int base = 0; base < NNODES; base += 1024) {
        int i = base + threadIdx.x;
        int v = (i < NNODES) ? cnt[i] : 0;
        s[threadIdx.x] = v;
        __syncthreads();
#pragma unroll
        for (int ofs = 1; ofs < 1024; ofs <<= 1) {
            int t = (threadIdx.x >= ofs) ? s[threadIdx.x - ofs] : 0;
            __syncthreads();
            s[threadIdx.x] += t;
            __syncthreads();
        }
        int excl = s[threadIdx.x] - v + carry;
        if (i < NNODES) { off[i] = excl; cur[i] = excl; }
        __syncthreads();
        if (threadIdx.x == 1023) carry += s[1023];
        __syncthreads();
    }
    if (threadIdx.x == 0) off[NNODES] = carry;
}
__global__ void fill_csr(const int* __restrict__ ei, int* __restrict__ cur,
                         int* __restrict__ csr_src)
{
    int e = blockIdx.x * blockDim.x + threadIdx.x;
    if (e < NEDGES) {
        int pos = atomicAdd(&cur[ei[NEDGES + e]], 1);
        csr_src[pos] = ei[e];
    }
}

// ---------------------------------------------------------------------------
// tf32-rounding prep kernels
// ---------------------------------------------------------------------------
__global__ void convert_x(const float4* __restrict__ x, float4* __restrict__ A) {
    const int F4 = DIM / 4;
    int i = blockIdx.x * blockDim.x + threadIdx.x;
    if (i >= NROWS_PAD * F4) return;
    int r = i / F4;
    float4 v = make_float4(0.f, 0.f, 0.f, 0.f);
    if (r < NNODES) {
        v = x[i];
        v.x = to_tf32(v.x); v.y = to_tf32(v.y);
        v.z = to_tf32(v.z); v.w = to_tf32(v.w);
    }
    A[i] = v;
}
__global__ void convert_w(const float4* __restrict__ Wl, const float4* __restrict__ Wr,
                          float4* __restrict__ W)
{
    const int F4 = DIM / 4;
    int i = blockIdx.x * blockDim.x + threadIdx.x;
    if (i >= NOUT * F4) return;
    float4 v = (i < DIM * F4) ? Wl[i] : Wr[i - DIM * F4];
    v.x = to_tf32(v.x); v.y = to_tf32(v.y);
    v.z = to_tf32(v.z); v.w = to_tf32(v.w);
    W[i] = v;
}

// ---------------------------------------------------------------------------
// Fused CSR aggregation + normalize + bias + residual (+relu/tf32) per node.
// ---------------------------------------------------------------------------
__global__ void __launch_bounds__(192) agg_combine(
    const float* __restrict__ T, const int* __restrict__ off,
    const int* __restrict__ csr_src, const float* __restrict__ bias,
    float* __restrict__ dst, int do_relu_round)
{
    const int d = blockIdx.x;
    const int t4 = threadIdx.x * 4;
    const int beg = off[d], end = off[d + 1];

    float4 acc = make_float4(0.f, 0.f, 0.f, 0.f);
    for (int i = beg; i < end; ++i) {
        int s = csr_src[i];
        float4 v = *(const float4*)(T + (size_t)s * NOUT + t4);
        acc.x += v.x; acc.y += v.y; acc.z += v.z; acc.w += v.w;
    }
    float inv = 1.0f / (float)max(end - beg, 1);
    float4 t = *(const float4*)(T + (size_t)d * NOUT + DIM + t4);
    float4 b = *(const float4*)(bias + t4);
    float4 v;
    v.x = acc.x * inv + b.x + t.x;
    v.y = acc.y * inv + b.y + t.y;
    v.z = acc.z * inv + b.z + t.z;
    v.w = acc.w * inv + b.w + t.w;
    if (do_relu_round) {
        v.x = to_tf32(fmaxf(v.x, 0.f)); v.y = to_tf32(fmaxf(v.y, 0.f));
        v.z = to_tf32(fmaxf(v.z, 0.f)); v.w = to_tf32(fmaxf(v.w, 0.f));
    }
    *(float4*)(dst + (size_t)d * DIM + t4) = v;
}

// ---------------------------------------------------------------------------
// tf32 mma.sync GEMM: T[128m x 256n] = A @ W^T (K=768)
// BM=128 BN=256 BK=32, 512 threads / 16 warps (2m x 8n), warp tile 64x32,
// 4-slot cp.async pipeline (wait 2, single sync/iter).
// ---------------------------------------------------------------------------
#define BM 128
#define BN 256
#define ROW_B 128
#define ATILE_B (BM * ROW_B)        // 16 KB
#define BTILE_B (BN * ROW_B)        // 32 KB
#define STG_B   (ATILE_B + BTILE_B) // 48 KB
#define SMEM_GEMM (4 * STG_B)       // 192 KB
#define NCH 24
#define AROW_BYTES (DIM * 4)

__device__ __forceinline__ void cp_async16(uint32_t saddr, const void* gaddr) {
    asm volatile("cp.async.cg.shared.global [%0], [%1], 16;"
                 :: "r"(saddr), "l"(gaddr));
}
__device__ __forceinline__ void cp_commit() {
    asm volatile("cp.async.commit_group;" ::: "memory");
}
__device__ __forceinline__ void cp_wait2() {
    asm volatile("cp.async.wait_group 2;" ::: "memory");
}
__device__ __forceinline__ void ldmatrix4(uint32_t* a, uint32_t addr) {
    asm volatile("ldmatrix.sync.aligned.m8n8.x4.shared.b16 {%0,%1,%2,%3}, [%4];"
                 : "=r"(a[0]), "=r"(a[1]), "=r"(a[2]), "=r"(a[3]) : "r"(addr));
}
__device__ __forceinline__ void mma_tf32(float* c, const uint32_t* a, const uint32_t* b) {
    asm volatile(
        "mma.sync.aligned.m16n8k8.row.col.f32.tf32.tf32.f32 "
        "{%0,%1,%2,%3}, {%4,%5,%6,%7}, {%8,%9}, {%0,%1,%2,%3};"
        : "+f"(c[0]), "+f"(c[1]), "+f"(c[2]), "+f"(c[3])
        : "r"(a[0]), "r"(a[1]), "r"(a[2]), "r"(a[3]), "r"(b[0]), "r"(b[1]));
}

// 512 threads: 6 cp.async each (2 A rows, 4 B rows)
__device__ __forceinline__ void load_stage(
    uint32_t slot_base, const char* Ab, const char* Bb, size_t goff, int tid)
{
    const int j  = tid & 7;        // 16B chunk in 128B row
    const int r0 = tid >> 3;       // 0..63
    const size_t gj = goff + (size_t)j * 16;
#pragma unroll
    for (int s = 0; s < 2; ++s) {
        int row = r0 + s * 64;
        uint32_t soff = row * ROW_B + ((j ^ (row & 7)) << 4);
        cp_async16(slot_base + soff, Ab + (size_t)row * AROW_BYTES + gj);
    }
#pragma unroll
    for (int s = 0; s < 4; ++s) {
        int row = r0 + s * 64;
        uint32_t soff = row * ROW_B + ((j ^ (row & 7)) << 4);
        cp_async16(slot_base + ATILE_B + soff, Bb + (size_t)row * AROW_BYTES + gj);
    }
}

__global__ void __launch_bounds__(512, 1) gemm_tf32(
    const float* __restrict__ A, const float* __restrict__ W,
    float* __restrict__ T)
{
    extern __shared__ char smem[];
    const uint32_t sb = smem_u32(smem);
    const int tid = threadIdx.x;
    const int wid = tid >> 5, lid = tid & 31;
    const int wm = (wid & 1) * 64;        // 2 m-warps
    const int wn = (wid >> 1) * 32;       // 8 n-warps
    const int n0 = blockIdx.x * BN;
    const int m0 = blockIdx.y * BM;

    const char* Ab = (const char*)A + (size_t)m0 * AROW_BYTES;
    const char* Bb = (const char*)W + (size_t)n0 * AROW_BYTES;

    float acc[4][4][4];                   // 64 accumulators
#pragma unroll
    for (int i = 0; i < 4; i++)
#pragma unroll
        for (int j = 0; j < 4; j++)
#pragma unroll
            for (int k = 0; k < 4; k++) acc[i][j][k] = 0.f;

#pragma unroll
    for (int p = 0; p < 3; ++p) {
        load_stage(sb + p * STG_B, Ab, Bb, (size_t)p * 128, tid);
        cp_commit();
    }

    // A frags (tf32 m16 layout): row = wm+mt*16 + (lid&7) + 8*((lid>>3)&1),
    //                            chunk bit = lid>>4
    uint32_t rowoffA[4], swzA[4];
    const uint32_t hiA = lid >> 4;
#pragma unroll
    for (int mt = 0; mt < 4; ++mt) {
        int r = wm + mt * 16 + (lid & 7) + ((lid >> 3) & 1) * 8;
        rowoffA[mt] = r * ROW_B;
        swzA[mt] = r & 7;
    }
    // B frags: bt 0..1 covers nt pairs; row = wn+bt*16 + (lid&7) + 8*(lid>>4),
    //          chunk bit = (lid>>3)&1
    uint32_t rowoffB[2], swzB[2];
    const uint32_t hiB = (lid >> 3) & 1;
#pragma unroll
    for (int bt = 0; bt < 2; ++bt) {
        int r = wn + bt * 16 + (lid & 7) + (lid >> 4) * 8;
        rowoffB[bt] = ATILE_B + r * ROW_B;
        swzB[bt] = r & 7;
    }

    for (int c = 0; c < NCH; ++c) {
        cp_wait2();
        __syncthreads();   // stage c visible; slot (c+3)&3 drained (iter c-1)

        const int cn = c + 3;
        if (cn < NCH) load_stage(sb + (cn & 3) * STG_B, Ab, Bb,
                                 (size_t)cn * 128, tid);
        cp_commit();

        const uint32_t sS = sb + (c & 3) * STG_B;
#pragma unroll
        for (int ks = 0; ks < 4; ++ks) {
            uint32_t bfrag[4][2];
#pragma unroll
            for (int bt = 0; bt < 2; ++bt) {
                uint32_t r[4];
                ldmatrix4(r, sS + rowoffB[bt] +
                             (((ks * 2 + hiB) ^ swzB[bt]) << 4));
                bfrag[bt * 2 + 0][0] = r[0]; bfrag[bt * 2 + 0][1] = r[1];
                bfrag[bt * 2 + 1][0] = r[2]; bfrag[bt * 2 + 1][1] = r[3];
            }
#pragma unroll
            for (int mt = 0; mt < 4; ++mt) {
                uint32_t afrag[4];
                ldmatrix4(afrag, sS + rowoffA[mt] +
                                 (((ks * 2 + hiA) ^ swzA[mt]) << 4));
#pragma unroll
                for (int nt = 0; nt < 4; ++nt)
                    mma_tf32(acc[mt][nt], afrag, bfrag[nt]);
            }
        }
    }

    // epilogue: raw fp32 store to T
#pragma unroll
    for (int mt = 0; mt < 4; ++mt) {
        int row_lo = m0 + wm + mt * 16 + (lid >> 2);
#pragma unroll
        for (int h = 0; h < 2; ++h) {
            int row = row_lo + h * 8;
            float* orow = T + (size_t)row * NOUT;
#pragma unroll
            for (int nt = 0; nt < 4; ++nt) {
                int col = n0 + wn + nt * 8 + (lid & 3) * 2;
                float2 v;
                v.x = acc[mt][nt][h * 2 + 0];
                v.y = acc[mt][nt][h * 2 + 1];
                *(float2*)(orow + col) = v;
            }
        }
    }
}

// ---------------------------------------------------------------------------
extern "C" void kernel_launch(void* const* d_in, const int* in_sizes, int n_in,
                              void* d_out, int out_size)
{
    const float* x   = (const float*)d_in[0];
    const int*   ei  = (const int*)d_in[1];     // int32 (JAX x64 disabled)
    const float* W1l = (const float*)d_in[2];
    const float* b1l = (const float*)d_in[3];
    const float* W1r = (const float*)d_in[4];
    const float* W2l = (const float*)d_in[5];
    const float* b2l = (const float*)d_in[6];
    const float* W2r = (const float*)d_in[7];
    float*       out = (float*)d_out;

    float *T, *A, *W1, *W2;
    int *cnt, *off, *cur, *csr;
    cudaGetSymbolAddress((void**)&T,   g_T);
    cudaGetSymbolAddress((void**)&A,   g_A);
    cudaGetSymbolAddress((void**)&W1,  g_W1);
    cudaGetSymbolAddress((void**)&W2,  g_W2);
    cudaGetSymbolAddress((void**)&cnt, g_cnt);
    cudaGetSymbolAddress((void**)&off, g_off);
    cudaGetSymbolAddress((void**)&cur, g_cur);
    cudaGetSymbolAddress((void**)&csr, g_csr_src);

    cudaFuncSetAttribute(gemm_tf32, cudaFuncAttributeMaxDynamicSharedMemorySize,
                         SMEM_GEMM);

    const int rows_blocks = (NROWS_PAD * (DIM / 4) + 255) / 256;
    const int w_blocks    = (NOUT * (DIM / 4) + 255) / 256;
    const int eb          = (NEDGES + 255) / 256;
    dim3 gg(NOUT / BN, NROWS_PAD / BM);   // (6, 391)

    // ---- Prep: CSR + conversions (both W's up front) ----
    zero_int<<<(NNODES + 255) / 256, 256>>>(cnt, NNODES);
    count_deg<<<eb, 256>>>(ei, cnt);
    exscan<<<1, 1024>>>(cnt, off, cur);
    fill_csr<<<eb, 256>>>(ei, cur, csr);
    convert_x<<<rows_blocks, 256>>>((const float4*)x, (float4*)A);
    convert_w<<<w_blocks, 256>>>((const float4*)W1l, (const float4*)W1r, (float4*)W1);
    convert_w<<<w_blocks, 256>>>((const float4*)W2l, (const float4*)W2r, (float4*)W2);

    // ---- Layer 1 ----
    gemm_tf32<<<gg, 512, SMEM_GEMM>>>(A, W1, T);
    agg_combine<<<NNODES, 192>>>(T, off, csr, b1l, A, 1);

    // ---- Layer 2 ----
    gemm_tf32<<<gg, 512, SMEM_GEMM>>>(A, W2, T);
    agg_combine<<<NNODES, 192>>>(T, off, csr, b2l, out, 0);
}

// round 9
// speedup vs baseline: 1.1187x; 1.1187x over previous
#include <cuda_runtime.h>
#include <cstdint>

#define NNODES    50000
#define NROWS_PAD 50048
#define NEDGES    100000
#define DIM       768
#define NOUT      1536       // T cols: [x@Wl^T (768) | x@Wr^T (768)]

// ---- scratch (allocation-free rule: __device__ globals) -------------------
__device__ float g_T[(size_t)NROWS_PAD * NOUT];             // 307 MB
__device__ float g_A[(size_t)NROWS_PAD * DIM];              // 154 MB (tf32-rounded)
__device__ float g_W1[(size_t)NOUT * DIM];                  // 4.7 MB
__device__ float g_W2[(size_t)NOUT * DIM];                  // 4.7 MB
__device__ int   g_cnt[NNODES];
__device__ int   g_off[NNODES + 1];
__device__ int   g_cur[NNODES];
__device__ int   g_csr_src[NEDGES];

// ---------------------------------------------------------------------------
__device__ __forceinline__ uint32_t smem_u32(const void* p) {
    uint32_t a;
    asm("{ .reg .u64 t; cvta.to.shared.u64 t, %1; cvt.u32.u64 %0, t; }"
        : "=r"(a) : "l"(p));
    return a;
}
__device__ __forceinline__ float to_tf32(float f) {
    uint32_t u;
    asm("cvt.rna.tf32.f32 %0, %1;" : "=r"(u) : "f"(f));
    return __uint_as_float(u);
}

// ---------------------------------------------------------------------------
// CSR build
// ---------------------------------------------------------------------------
__global__ void zero_int(int* __restrict__ p, int n) {
    int i = blockIdx.x * blockDim.x + threadIdx.x;
    if (i < n) p[i] = 0;
}
__global__ void count_deg(const int* __restrict__ ei, int* __restrict__ cnt) {
    int e = blockIdx.x * blockDim.x + threadIdx.x;
    if (e < NEDGES) atomicAdd(&cnt[ei[NEDGES + e]], 1);
}
__global__ void __launch_bounds__(1024) exscan(
    const int* __restrict__ cnt, int* __restrict__ off, int* __restrict__ cur)
{
    __shared__ int s[1024];
    __shared__ int carry;
    if (threadIdx.x == 0) carry = 0;
    __syncthreads();
    for (int base = 0; base < NNODES; base += 1024) {
        int i = base + threadIdx.x;
        int v = (i < NNODES) ? cnt[i] : 0;
        s[threadIdx.x] = v;
        __syncthreads();
#pragma unroll
        for (int ofs = 1; ofs < 1024; ofs <<= 1) {
            int t = (threadIdx.x >= ofs) ? s[threadIdx.x - ofs] : 0;
            __syncthreads();
            s[threadIdx.x] += t;
            __syncthreads();
        }
        int excl = s[threadIdx.x] - v + carry;
        if (i < NNODES) { off[i] = excl; cur[i] = excl; }
        __syncthreads();
        if (threadIdx.x == 1023) carry += s[1023];
        __syncthreads();
    }
    if (threadIdx.x == 0) off[NNODES] = carry;
}
__global__ void fill_csr(const int* __restrict__ ei, int* __restrict__ cur,
                         int* __restrict__ csr_src)
{
    int e = blockIdx.x * blockDim.x + threadIdx.x;
    if (e < NEDGES) {
        int pos = atomicAdd(&cur[ei[NEDGES + e]], 1);
        csr_src[pos] = ei[e];
    }
}

// ---------------------------------------------------------------------------
// tf32-rounding prep kernels
// ---------------------------------------------------------------------------
__global__ void convert_x(const float4* __restrict__ x, float4* __restrict__ A) {
    const int F4 = DIM / 4;
    int i = blockIdx.x * blockDim.x + threadIdx.x;
    if (i >= NROWS_PAD * F4) return;
    int r = i / F4;
    float4 v = make_float4(0.f, 0.f, 0.f, 0.f);
    if (r < NNODES) {
        v = x[i];
        v.x = to_tf32(v.x); v.y = to_tf32(v.y);
        v.z = to_tf32(v.z); v.w = to_tf32(v.w);
    }
    A[i] = v;
}
__global__ void convert_w(const float4* __restrict__ Wl, const float4* __restrict__ Wr,
                          float4* __restrict__ W)
{
    const int F4 = DIM / 4;
    int i = blockIdx.x * blockDim.x + threadIdx.x;
    if (i >= NOUT * F4) return;
    float4 v = (i < DIM * F4) ? Wl[i] : Wr[i - DIM * F4];
    v.x = to_tf32(v.x); v.y = to_tf32(v.y);
    v.z = to_tf32(v.z); v.w = to_tf32(v.w);
    W[i] = v;
}

// ---------------------------------------------------------------------------
// Fused CSR aggregation + normalize + bias + residual (+relu/tf32) per node.
// ---------------------------------------------------------------------------
__global__ void __launch_bounds__(192) agg_combine(
    const float* __restrict__ T, const int* __restrict__ off,
    const int* __restrict__ csr_src, const float* __restrict__ bias,
    float* __restrict__ dst, int do_relu_round)
{
    const int d = blockIdx.x;
    const int t4 = threadIdx.x * 4;
    const int beg = off[d], end = off[d + 1];

    float4 acc = make_float4(0.f, 0.f, 0.f, 0.f);
    for (int i = beg; i < end; ++i) {
        int s = csr_src[i];
        float4 v = *(const float4*)(T + (size_t)s * NOUT + t4);
        acc.x += v.x; acc.y += v.y; acc.z += v.z; acc.w += v.w;
    }
    float inv = 1.0f / (float)max(end - beg, 1);
    float4 t = *(const float4*)(T + (size_t)d * NOUT + DIM + t4);
    float4 b = *(const float4*)(bias + t4);
    float4 v;
    v.x = acc.x * inv + b.x + t.x;
    v.y = acc.y * inv + b.y + t.y;
    v.z = acc.z * inv + b.z + t.z;
    v.w = acc.w * inv + b.w + t.w;
    if (do_relu_round) {
        v.x = to_tf32(fmaxf(v.x, 0.f)); v.y = to_tf32(fmaxf(v.y, 0.f));
        v.z = to_tf32(fmaxf(v.z, 0.f)); v.w = to_tf32(fmaxf(v.w, 0.f));
    }
    *(float4*)(dst + (size_t)d * DIM + t4) = v;
}

// ---------------------------------------------------------------------------
// tf32 mma.sync GEMM: T[128m x 128n] = A @ W^T (K=768)
// BM=128 BN=128 BK=32, 256 threads / 8 warps (2m x 4n), warp tile 64x32,
// 3-slot cp.async pipeline (32KB stages), 2 CTAs/SM for cross-CTA overlap.
// ---------------------------------------------------------------------------
#define BM 128
#define BN 128
#define ROW_B 128
#define ATILE_B (BM * ROW_B)        // 16 KB
#define BTILE_B (BN * ROW_B)        // 16 KB
#define STG_B   (ATILE_B + BTILE_B) // 32 KB
#define NSLOT 3
#define SMEM_GEMM (NSLOT * STG_B)   // 96 KB
#define NCH 24
#define AROW_BYTES (DIM * 4)

__device__ __forceinline__ void cp_async16(uint32_t saddr, const void* gaddr) {
    asm volatile("cp.async.cg.shared.global [%0], [%1], 16;"
                 :: "r"(saddr), "l"(gaddr));
}
__device__ __forceinline__ void cp_commit() {
    asm volatile("cp.async.commit_group;" ::: "memory");
}
__device__ __forceinline__ void cp_wait1() {
    asm volatile("cp.async.wait_group 1;" ::: "memory");
}
__device__ __forceinline__ void ldmatrix4(uint32_t* a, uint32_t addr) {
    asm volatile("ldmatrix.sync.aligned.m8n8.x4.shared.b16 {%0,%1,%2,%3}, [%4];"
                 : "=r"(a[0]), "=r"(a[1]), "=r"(a[2]), "=r"(a[3]) : "r"(addr));
}
__device__ __forceinline__ void mma_tf32(float* c, const uint32_t* a, const uint32_t* b) {
    asm volatile(
        "mma.sync.aligned.m16n8k8.row.col.f32.tf32.tf32.f32 "
        "{%0,%1,%2,%3}, {%4,%5,%6,%7}, {%8,%9}, {%0,%1,%2,%3};"
        : "+f"(c[0]), "+f"(c[1]), "+f"(c[2]), "+f"(c[3])
        : "r"(a[0]), "r"(a[1]), "r"(a[2]), "r"(a[3]), "r"(b[0]), "r"(b[1]));
}

// 256 threads: 8 cp.async each (4 A rows, 4 B rows)
__device__ __forceinline__ void load_stage(
    uint32_t slot_base, const char* Ab, const char* Bb, size_t goff, int tid)
{
    const int j  = tid & 7;        // 16B chunk in 128B row
    const int r0 = tid >> 3;       // 0..31
    const size_t gj = goff + (size_t)j * 16;
#pragma unroll
    for (int s = 0; s < 4; ++s) {
        int row = r0 + s * 32;
        uint32_t soff = row * ROW_B + ((j ^ (row & 7)) << 4);
        cp_async16(slot_base + soff, Ab + (size_t)row * AROW_BYTES + gj);
        cp_async16(slot_base + ATILE_B + soff, Bb + (size_t)row * AROW_BYTES + gj);
    }
}

__global__ void __launch_bounds__(256, 2) gemm_tf32(
    const float* __restrict__ A, const float* __restrict__ W,
    float* __restrict__ T)
{
    extern __shared__ char smem[];
    const uint32_t sb = smem_u32(smem);
    const int tid = threadIdx.x;
    const int wid = tid >> 5, lid = tid & 31;
    const int wm = (wid & 1) * 64;        // 2 m-warps
    const int wn = (wid >> 1) * 32;       // 4 n-warps
    const int n0 = blockIdx.x * BN;
    const int m0 = blockIdx.y * BM;

    const char* Ab = (const char*)A + (size_t)m0 * AROW_BYTES;
    const char* Bb = (const char*)W + (size_t)n0 * AROW_BYTES;

    float acc[4][4][4];                   // 64 accumulators
#pragma unroll
    for (int i = 0; i < 4; i++)
#pragma unroll
        for (int j = 0; j < 4; j++)
#pragma unroll
            for (int k = 0; k < 4; k++) acc[i][j][k] = 0.f;

#pragma unroll
    for (int p = 0; p < 2; ++p) {
        load_stage(sb + p * STG_B, Ab, Bb, (size_t)p * 128, tid);
        cp_commit();
    }

    // A frags (tf32 m16 layout): row = wm+mt*16 + (lid&7) + 8*((lid>>3)&1),
    //                            chunk bit = lid>>4
    uint32_t rowoffA[4], swzA[4];
    const uint32_t hiA = lid >> 4;
#pragma unroll
    for (int mt = 0; mt < 4; ++mt) {
        int r = wm + mt * 16 + (lid & 7) + ((lid >> 3) & 1) * 8;
        rowoffA[mt] = r * ROW_B;
        swzA[mt] = r & 7;
    }
    // B frags: bt 0..1; row = wn+bt*16 + (lid&7) + 8*(lid>>4),
    //          chunk bit = (lid>>3)&1
    uint32_t rowoffB[2], swzB[2];
    const uint32_t hiB = (lid >> 3) & 1;
#pragma unroll
    for (int bt = 0; bt < 2; ++bt) {
        int r = wn + bt * 16 + (lid & 7) + (lid >> 4) * 8;
        rowoffB[bt] = ATILE_B + r * ROW_B;
        swzB[bt] = r & 7;
    }

    int slot = 0;
    for (int c = 0; c < NCH; ++c) {
        cp_wait1();
        __syncthreads();   // stage c ready; all warps done reading stage c-1

        const int cn = c + 2;
        const int wslot = (slot + 2 >= NSLOT) ? slot + 2 - NSLOT : slot + 2;
        if (cn < NCH) load_stage(sb + wslot * STG_B, Ab, Bb,
                                 (size_t)cn * 128, tid);
        cp_commit();

        const uint32_t sS = sb + slot * STG_B;
#pragma unroll
        for (int ks = 0; ks < 4; ++ks) {
            uint32_t bfrag[4][2];
#pragma unroll
            for (int bt = 0; bt < 2; ++bt) {
                uint32_t r[4];
                ldmatrix4(r, sS + rowoffB[bt] +
                             (((ks * 2 + hiB) ^ swzB[bt]) << 4));
                bfrag[bt * 2 + 0][0] = r[0]; bfrag[bt * 2 + 0][1] = r[1];
                bfrag[bt * 2 + 1][0] = r[2]; bfrag[bt * 2 + 1][1] = r[3];
            }
#pragma unroll
            for (int mt = 0; mt < 4; ++mt) {
                uint32_t afrag[4];
                ldmatrix4(afrag, sS + rowoffA[mt] +
                                 (((ks * 2 + hiA) ^ swzA[mt]) << 4));
#pragma unroll
                for (int nt = 0; nt < 4; ++nt)
                    mma_tf32(acc[mt][nt], afrag, bfrag[nt]);
            }
        }
        slot = (slot + 1 == NSLOT) ? 0 : slot + 1;
    }

    // epilogue: raw fp32 store to T
#pragma unroll
    for (int mt = 0; mt < 4; ++mt) {
        int row_lo = m0 + wm + mt * 16 + (lid >> 2);
#pragma unroll
        for (int h = 0; h < 2; ++h) {
            int row = row_lo + h * 8;
            float* orow = T + (size_t)row * NOUT;
#pragma unroll
            for (int nt = 0; nt < 4; ++nt) {
                int col = n0 + wn + nt * 8 + (lid & 3) * 2;
                float2 v;
                v.x = acc[mt][nt][h * 2 + 0];
                v.y = acc[mt][nt][h * 2 + 1];
                *(float2*)(orow + col) = v;
            }
        }
    }
}

// ---------------------------------------------------------------------------
extern "C" void kernel_launch(void* const* d_in, const int* in_sizes, int n_in,
                              void* d_out, int out_size)
{
    const float* x   = (const float*)d_in[0];
    const int*   ei  = (const int*)d_in[1];     // int32 (JAX x64 disabled)
    const float* W1l = (const float*)d_in[2];
    const float* b1l = (const float*)d_in[3];
    const float* W1r = (const float*)d_in[4];
    const float* W2l = (const float*)d_in[5];
    const float* b2l = (const float*)d_in[6];
    const float* W2r = (const float*)d_in[7];
    float*       out = (float*)d_out;

    float *T, *A, *W1, *W2;
    int *cnt, *off, *cur, *csr;
    cudaGetSymbolAddress((void**)&T,   g_T);
    cudaGetSymbolAddress((void**)&A,   g_A);
    cudaGetSymbolAddress((void**)&W1,  g_W1);
    cudaGetSymbolAddress((void**)&W2,  g_W2);
    cudaGetSymbolAddress((void**)&cnt, g_cnt);
    cudaGetSymbolAddress((void**)&off, g_off);
    cudaGetSymbolAddress((void**)&cur, g_cur);
    cudaGetSymbolAddress((void**)&csr, g_csr_src);

    cudaFuncSetAttribute(gemm_tf32, cudaFuncAttributeMaxDynamicSharedMemorySize,
                         SMEM_GEMM);

    const int rows_blocks = (NROWS_PAD * (DIM / 4) + 255) / 256;
    const int w_blocks    = (NOUT * (DIM / 4) + 255) / 256;
    const int eb          = (NEDGES + 255) / 256;
    dim3 gg(NOUT / BN, NROWS_PAD / BM);   // (12, 391)

    // ---- Prep (ordered so gemm_tf32 is launch #6 for ncu -s 5 -c 1) ----
    convert_x<<<rows_blocks, 256>>>((const float4*)x, (float4*)A);              // 1
    convert_w<<<w_blocks, 256>>>((const float4*)W1l, (const float4*)W1r,
                                 (float4*)W1);                                  // 2
    convert_w<<<w_blocks, 256>>>((const float4*)W2l, (const float4*)W2r,
                                 (float4*)W2);                                  // 3
    zero_int<<<(NNODES + 255) / 256, 256>>>(cnt, NNODES);                       // 4
    count_deg<<<eb, 256>>>(ei, cnt);                                            // 5

    // ---- Layer 1 ----
    gemm_tf32<<<gg, 256, SMEM_GEMM>>>(A, W1, T);                                // 6 (profiled)
    exscan<<<1, 1024>>>(cnt, off, cur);                                         // 7
    fill_csr<<<eb, 256>>>(ei, cur, csr);                                        // 8
    agg_combine<<<NNODES, 192>>>(T, off, csr, b1l, A, 1);                       // 9

    // ---- Layer 2 ----
    gemm_tf32<<<gg, 256, SMEM_GEMM>>>(A, W2, T);                                // 10
    agg_combine<<<NNODES, 192>>>(T, off, csr, b2l, out, 0);                     // 11
}